// round 4
// baseline (speedup 1.0000x reference)
#include <cuda_runtime.h>
#include <math.h>

#define NBOX   4096
#define NFRAME 4
#define CAP    128
#define MAXC   16
#define INL    8
#define IOU_T   0.3f
#define SCORE_T 0.2f

// ---------------- scratch (static __device__, no allocations) ----------------
__device__ float d_sbox  [NFRAME*NBOX*7];
__device__ float d_sscore[NFRAME*NBOX];
__device__ float d_slabel[NFRAME*NBOX];
__device__ float d_x1[NFRAME*NBOX], d_x2[NFRAME*NBOX];
__device__ float d_y1[NFRAME*NBOX], d_y2[NFRAME*NBOX];
__device__ float d_areaA[NFRAME*NBOX];
__device__ int   d_V[NFRAME];
__device__ int   d_nbr[NFRAME*NBOX*CAP];
__device__ int   d_deg[NFRAME*NBOX];
__device__ int   d_selfpos[NFRAME*NBOX];
__device__ int   d_clusIdx[NFRAME*NBOX*MAXC];
__device__ int   d_count[NFRAME*NBOX];
__device__ int   d_lead[NFRAME*NBOX];

// ---------------- kernel 1: stable radix sort by score desc + gather --------
// 2-bit LSD radix, 16 passes, keys = ~sortable(score-key) ascending
// (=> score descending, ties by ascending original index via stability)
__global__ void __launch_bounds__(1024) k_sort(const float* __restrict__ boxes,
                                               const float* __restrict__ scores,
                                               const int*   __restrict__ labels)
{
    extern __shared__ char sm[];
    unsigned*       kb = (unsigned*)sm;                         // [2][NBOX]
    unsigned short* pb = (unsigned short*)(sm + 2*NBOX*4);      // [2][NBOX]
    __shared__ unsigned wsumA[32], wsumB[32];
    __shared__ int vcount;

    int f = blockIdx.x, tid = threadIdx.x, lane = tid & 31, wid = tid >> 5;
    const float* sc = scores + f*NBOX;
    if (tid == 0) vcount = 0;
    int vloc = 0;
    for (int i = tid; i < NBOX; i += 1024) {
        float s = sc[i];
        bool v = (s > SCORE_T);
        float skey = v ? s : -INFINITY;
        unsigned u = __float_as_uint(skey);
        u = (u & 0x80000000u) ? ~u : (u | 0x80000000u);
        kb[i] = ~u;
        pb[i] = (unsigned short)i;
        vloc += v ? 1 : 0;
    }
    #pragma unroll
    for (int o = 16; o; o >>= 1) vloc += __shfl_xor_sync(0xffffffffu, vloc, o);
    if (lane == 0) atomicAdd(&vcount, vloc);
    __syncthreads();

    int cur = 0;
    for (int pass = 0; pass < 16; ++pass) {
        int sh = pass * 2;
        unsigned* kc = kb + cur*NBOX;  unsigned short* pc = pb + cur*NBOX;
        unsigned* kn = kb + (cur^1)*NBOX; unsigned short* pn = pb + (cur^1)*NBOX;
        int b0 = tid*4;
        unsigned k0=kc[b0],k1=kc[b0+1],k2=kc[b0+2],k3=kc[b0+3];
        unsigned short q0=pc[b0],q1=pc[b0+1],q2=pc[b0+2],q3=pc[b0+3];
        int d0=(k0>>sh)&3, d1=(k1>>sh)&3, d2=(k2>>sh)&3, d3=(k3>>sh)&3;
        unsigned cA=0, cB=0;
        #define ADDC(d) { if((d)==0) cA+=1u; else if((d)==1) cA+=(1u<<16); \
                          else if((d)==2) cB+=1u; else cB+=(1u<<16); }
        ADDC(d0) ADDC(d1) ADDC(d2) ADDC(d3)
        unsigned a=cA, b=cB;
        #pragma unroll
        for (int o=1;o<32;o<<=1){
            unsigned ta=__shfl_up_sync(0xffffffffu,a,o);
            unsigned tb=__shfl_up_sync(0xffffffffu,b,o);
            if(lane>=o){a+=ta;b+=tb;}
        }
        if (lane==31){ wsumA[wid]=a; wsumB[wid]=b; }
        __syncthreads();
        if (wid==0){
            unsigned x=wsumA[lane], y=wsumB[lane];
            #pragma unroll
            for(int o=1;o<32;o<<=1){
                unsigned tx=__shfl_up_sync(0xffffffffu,x,o);
                unsigned ty=__shfl_up_sync(0xffffffffu,y,o);
                if(lane>=o){x+=tx;y+=ty;}
            }
            wsumA[lane]=x; wsumB[lane]=y;
        }
        __syncthreads();
        unsigned wa = wid ? wsumA[wid-1] : 0u, wb = wid ? wsumB[wid-1] : 0u;
        unsigned exA = a - cA + wa, exB = b - cB + wb;   // thread-exclusive per bucket
        unsigned totA = wsumA[31], totB = wsumB[31];
        unsigned T0 = totA & 0xffffu, T1 = totA >> 16, T2 = totB & 0xffffu;
        unsigned base0=0, base1=T0, base2=T0+T1, base3=base2+T2;
        unsigned off[4];
        off[0]=base0+(exA&0xffffu); off[1]=base1+(exA>>16);
        off[2]=base2+(exB&0xffffu); off[3]=base3+(exB>>16);
        unsigned dd;
        dd=off[d0]++; kn[dd]=k0; pn[dd]=q0;
        dd=off[d1]++; kn[dd]=k1; pn[dd]=q1;
        dd=off[d2]++; kn[dd]=k2; pn[dd]=q2;
        dd=off[d3]++; kn[dd]=k3; pn[dd]=q3;
        __syncthreads();
        cur ^= 1;
    }
    if (tid == 0) d_V[f] = vcount;

    unsigned short* pf = pb + cur*NBOX;
    for (int r = tid; r < NBOX; r += 1024) {
        int o = pf[r];
        const float* bx = boxes + ((size_t)f*NBOX + o)*7;
        float b0 = bx[0], b1 = bx[1], b2 = bx[2], b3 = bx[3],
              b4 = bx[4], b5 = bx[5], b6 = bx[6];
        float s  = sc[o];
        int  lab = labels[f*NBOX + o];
        float off = (float)lab * 10000.0f;
        float cx = b0 + off, cy = b1;
        float hx = b3 * 0.5f, hy = b4 * 0.5f;
        float x1 = cx - hx, x2 = cx + hx, y1 = cy - hy, y2 = cy + hy;
        float area = (x2 - x1) * (y2 - y1);
        int idx = f*NBOX + r;
        float* sb = d_sbox + (size_t)idx*7;
        sb[0]=b0; sb[1]=b1; sb[2]=b2; sb[3]=b3; sb[4]=b4; sb[5]=b5; sb[6]=b6;
        d_sscore[idx] = s; d_slabel[idx] = (float)lab;
        d_x1[idx]=x1; d_x2[idx]=x2; d_y1[idx]=y1; d_y2[idx]=y2; d_areaA[idx]=area;
    }
}

// ---------------- kernel 2: ascending neighbor lists (IoU > thres) ----------
__global__ void __launch_bounds__(128) k_nbr()
{
    int f   = blockIdx.y;
    int V   = d_V[f];
    int i0  = blockIdx.x * 128;
    int tid = threadIdx.x;
    int i   = i0 + tid;
    int base = f*NBOX;
    bool act = (i < V);
    if (i < NBOX && !act) d_deg[base + i] = 0;
    if (i0 >= V) return;

    float xi1=0,xi2=0,yi1=0,yi2=0,ai=0;
    if (act) { xi1=d_x1[base+i]; xi2=d_x2[base+i];
               yi1=d_y1[base+i]; yi2=d_y2[base+i]; ai=d_areaA[base+i]; }
    __shared__ float sx1[128], sx2[128], sy1[128], sy2[128], sa[128];
    int  cnt  = 0;
    int  sp   = 0;
    int* lst  = d_nbr + ((size_t)(base + i)) * CAP;
    for (int j0 = 0; j0 < V; j0 += 128) {
        __syncthreads();
        int j = j0 + tid;
        if (j < V) { sx1[tid]=d_x1[base+j]; sx2[tid]=d_x2[base+j];
                     sy1[tid]=d_y1[base+j]; sy2[tid]=d_y2[base+j]; sa[tid]=d_areaA[base+j]; }
        __syncthreads();
        int lim = min(128, V - j0);
        if (act) {
            #pragma unroll 2
            for (int jj = 0; jj < lim; ++jj) {
                float ix = fminf(xi2, sx2[jj]) - fmaxf(xi1, sx1[jj]);
                if (ix > 0.f) {
                    float iy = fminf(yi2, sy2[jj]) - fmaxf(yi1, sy1[jj]);
                    if (iy > 0.f) {
                        float inter = ix * iy;
                        float den   = fmaxf(ai + sa[jj] - inter, 1e-6f);
                        float iou   = inter / den;
                        if (iou > IOU_T && cnt < CAP) {
                            if (j0 + jj == i) sp = cnt;
                            lst[cnt++] = j0 + jj;
                        }
                    }
                }
            }
        }
    }
    if (act) { d_deg[base + i] = cnt; d_selfpos[base + i] = sp; }
}

// ---------------- kernel 3: parallel lex-first greedy, shared-cached --------
__global__ void __launch_bounds__(1024) k_scan()
{
    extern __shared__ char sm[];
    unsigned short* inl  = (unsigned short*)sm;                       // NBOX*INL
    unsigned short* spA  = (unsigned short*)(sm + NBOX*INL*2);        // NBOX
    unsigned short* cid  = spA + NBOX;                                // NBOX
    unsigned char*  state= (unsigned char*)(cid + NBOX);              // NBOX
    __shared__ int changed;
    volatile unsigned char* vstate = state;

    int f = blockIdx.x, tid = threadIdx.x;
    int base = f*NBOX;
    int V = d_V[f];

    for (int i = tid; i < NBOX; i += 1024) {
        d_lead[base + i] = 0;
        state[i] = (i < V) ? (unsigned char)0 : (unsigned char)2;
    }
    for (int i = tid; i < V; i += 1024) {
        int sp = d_selfpos[base + i];
        spA[i] = (unsigned short)sp;
        const int* g = d_nbr + (size_t)(base + i) * CAP;
        int m = sp < INL ? sp : INL;
        for (int k = 0; k < m; ++k) inl[i*INL + k] = (unsigned short)g[k];
    }
    __syncthreads();

    for (int round = 0; round < 4096; ++round) {
        if (tid == 0) changed = 0;
        __syncthreads();
        for (int rep = 0; rep < 2; ++rep) {
            int i0 = tid * 4;
            #pragma unroll
            for (int u = 0; u < 4; ++u) {
                int i = i0 + u;
                if (vstate[i] != 0) continue;
                int sp = spA[i];
                bool any1 = false, any0 = false;
                int m = sp < INL ? sp : INL;
                for (int k = 0; k < m; ++k) {
                    unsigned char s = vstate[inl[i*INL + k]];
                    any1 |= (s == 1); any0 |= (s == 0);
                }
                if (sp > INL && !any1) {
                    const int* g = d_nbr + (size_t)(base + i) * CAP;
                    for (int k = INL; k < sp && !any1; ++k) {
                        unsigned char s = vstate[g[k]];
                        any1 |= (s == 1); any0 |= (s == 0);
                    }
                }
                if (any1)       { vstate[i] = 2; changed = 1; }
                else if (!any0) { vstate[i] = 1; changed = 1; }
            }
        }
        __syncthreads();
        if (!changed) break;
        __syncthreads();
    }

    // cluster ids (min leader among ascending in-neighbors)
    for (int i = tid; i < V; i += 1024) {
        if (state[i] == 1) { cid[i] = (unsigned short)i; continue; }
        int sp = spA[i];
        int c = 0xFFFF;
        int m = sp < INL ? sp : INL;
        for (int k = 0; k < m; ++k) {
            int j = inl[i*INL + k];
            if (state[j] == 1) { c = j; break; }
        }
        if (c == 0xFFFF && sp > INL) {
            const int* g = d_nbr + (size_t)(base + i) * CAP;
            for (int k = INL; k < sp; ++k) {
                int j = g[k];
                if (state[j] == 1) { c = j; break; }
            }
        }
        cid[i] = (unsigned short)c;
    }
    __syncthreads();

    // leaders: member lists in ascending order (rank 0 = leader itself)
    for (int i = tid; i < V; i += 1024) {
        if (state[i] != 1) continue;
        int* outl = d_clusIdx + (base + i)*MAXC;
        outl[0] = i;
        const int* lst = d_nbr + (size_t)(base + i) * CAP;
        int sp = spA[i], dg = d_deg[base + i];
        int r = 1;
        for (int k = sp + 1; k < dg; ++k) {
            int m = lst[k];
            if (cid[m] == (unsigned short)i) { if (r < MAXC) outl[r] = m; ++r; }
        }
        d_count[base + i] = (r < MAXC) ? r : MAXC;
        d_lead [base + i] = 1;
    }
}

// ---------------- kernel 4: MLP + softmax merge + output --------------------
__global__ void __launch_bounds__(256) k_merge(const float* __restrict__ W1,
                                               const float* __restrict__ b1,
                                               const float* __restrict__ W2,
                                               const float* __restrict__ b2,
                                               float* __restrict__ out, int writeLead)
{
    __shared__ float sW1[448], sb1[64], sW2[64];
    __shared__ float sb2;
    int tid = threadIdx.x;
    for (int t = tid; t < 448; t += 256) sW1[t] = W1[t];
    if (tid < 64) { sb1[tid] = b1[tid]; sW2[tid] = W2[tid]; }
    if (tid == 0) sb2 = b2[0];
    __syncthreads();

    int g = tid >> 4, l = tid & 15;
    unsigned gm = 0xFFFFu << (tid & 16);
    int row = blockIdx.x * 16 + g;
    float* infoOut = out + (size_t)row * 9;
    int lead = d_lead[row];
    if (!lead) {
        if (l == 0) {
            #pragma unroll
            for (int d = 0; d < 9; ++d) infoOut[d] = 0.f;
            if (writeLead) out[(size_t)NFRAME*NBOX*9 + row] = 0.f;
        }
        return;
    }
    int cnt = d_count[row];
    if (cnt == 1) {
        // softmax over single valid slot = (1,0,...) exactly -> merged == own box
        if (l == 0) {
            const float* own = d_sbox + (size_t)row * 7;
            infoOut[0]=own[0]; infoOut[1]=own[1]; infoOut[2]=own[2];
            infoOut[3]=own[3]; infoOut[4]=own[4]; infoOut[5]=own[5];
            infoOut[6]=own[6];
            infoOut[7]=d_sscore[row];
            infoOut[8]=d_slabel[row];
            if (writeLead) out[(size_t)NFRAME*NBOX*9 + row] = 1.f;
        }
        return;
    }
    bool ok = l < cnt;
    float c[7];
    int f = row >> 12;
    if (ok) {
        int nb = d_clusIdx[row*MAXC + l];
        const float* sp = d_sbox + ((size_t)(f*NBOX) + nb) * 7;
        #pragma unroll
        for (int d = 0; d < 7; ++d) c[d] = sp[d];
    } else {
        #pragma unroll
        for (int d = 0; d < 7; ++d) c[d] = 0.f;
    }
    float logit;
    if (ok) {
        float lg = 0.f;
        for (int k = 0; k < 64; ++k) {
            float h = sb1[k];
            #pragma unroll
            for (int d = 0; d < 7; ++d) h += c[d] * sW1[d*64 + k];
            h = fmaxf(h, 0.f);
            lg += h * sW2[k];
        }
        logit = lg + sb2;
    } else logit = -1e9f;

    float m = logit;
    #pragma unroll
    for (int o = 8; o; o >>= 1) m = fmaxf(m, __shfl_xor_sync(gm, m, o, 16));
    float p = ok ? expf(logit - m) : 0.f;
    float S = p;
    #pragma unroll
    for (int o = 8; o; o >>= 1) S += __shfl_xor_sync(gm, S, o, 16);
    float w = p / S;
    float mg[7];
    #pragma unroll
    for (int d = 0; d < 7; ++d) {
        float v = w * c[d];
        #pragma unroll
        for (int o = 8; o; o >>= 1) v += __shfl_xor_sync(gm, v, o, 16);
        mg[d] = v;
    }
    if (l == 0) {
        const float* own = d_sbox + (size_t)row * 7;
        infoOut[0] = mg[0]; infoOut[1] = mg[1]; infoOut[2] = mg[2];
        infoOut[3] = (mg[3] <= 0.f) ? own[3] : mg[3];
        infoOut[4] = (mg[4] <= 0.f) ? own[4] : mg[4];
        infoOut[5] = (mg[5] <= 0.f) ? own[5] : mg[5];
        infoOut[6] = mg[6];
        infoOut[7] = d_sscore[row];
        infoOut[8] = d_slabel[row];
        if (writeLead) out[(size_t)NFRAME*NBOX*9 + row] = 1.f;
    }
}

// ---------------- launch -----------------------------------------------------
extern "C" void kernel_launch(void* const* d_in, const int* in_sizes, int n_in,
                              void* d_out, int out_size)
{
    const float* boxes  = (const float*)d_in[0];
    const float* scores = (const float*)d_in[1];
    const int*   labels = (const int*)  d_in[2];
    const float* W1     = (const float*)d_in[3];
    const float* b1     = (const float*)d_in[4];
    const float* W2     = (const float*)d_in[5];
    const float* b2     = (const float*)d_in[6];
    float* out = (float*)d_out;

    int writeLead = (out_size >= NFRAME*NBOX*10) ? 1 : 0;

    const int SMEM_SORT = 2*NBOX*4 + 2*NBOX*2;                    // 49152
    const int SMEM_SCAN = NBOX*INL*2 + NBOX*2*2 + NBOX;           // 86016
    static int inited = 0;
    if (!inited) {
        cudaFuncSetAttribute(k_sort, cudaFuncAttributeMaxDynamicSharedMemorySize, SMEM_SORT);
        cudaFuncSetAttribute(k_scan, cudaFuncAttributeMaxDynamicSharedMemorySize, SMEM_SCAN);
        inited = 1;
    }

    k_sort<<<NFRAME, 1024, SMEM_SORT>>>(boxes, scores, labels);
    k_nbr<<<dim3(NBOX/128, NFRAME), 128>>>();
    k_scan<<<NFRAME, 1024, SMEM_SCAN>>>();
    k_merge<<<(NFRAME*NBOX)/16, 256>>>(W1, b1, W2, b2, out, writeLead);
}

// round 7
// speedup vs baseline: 2.1643x; 2.1643x over previous
#include <cuda_runtime.h>
#include <math.h>

#define NBOX   4096
#define NFRAME 4
#define CAP    128
#define MAXC   16
#define INL    8
#define IOU_T   0.3f
#define SCORE_T 0.2f
#define SKW(i) ((i) + ((i) >> 5))

// ---------------- scratch (static __device__, no allocations) ----------------
__device__ float d_sbox  [NFRAME*NBOX*7];
__device__ float d_sscore[NFRAME*NBOX];
__device__ float d_slabel[NFRAME*NBOX];
__device__ float d_x1[NFRAME*NBOX], d_x2[NFRAME*NBOX];
__device__ float d_y1[NFRAME*NBOX], d_y2[NFRAME*NBOX];
__device__ float d_areaA[NFRAME*NBOX];
__device__ int   d_V[NFRAME];
__device__ int   d_Vc[NFRAME*3];
__device__ float4 d_clsGeo [NFRAME*3*NBOX];   // (x1,x2,y1,y2) per class entry
__device__ float  d_clsArea[NFRAME*3*NBOX];
__device__ int    d_clsG   [NFRAME*3*NBOX];   // global sorted index
__device__ int   d_nbr[NFRAME*NBOX*CAP];
__device__ int   d_deg[NFRAME*NBOX];
__device__ int   d_selfpos[NFRAME*NBOX];
__device__ int   d_clusIdx[NFRAME*NBOX*MAXC];
__device__ int   d_count[NFRAME*NBOX];
__device__ int   d_lead[NFRAME*NBOX];

// ---------------- kernel 1: stable radix sort + gather + class partition ----
__global__ void __launch_bounds__(1024) k_sort(const float* __restrict__ boxes,
                                               const float* __restrict__ scores,
                                               const int*   __restrict__ labels)
{
    extern __shared__ unsigned sm[];
    unsigned* kb = sm;                 // [2][4224] keys (skewed)
    unsigned* pb = sm + 2*4224;        // [2][4224] payload (skewed)
    __shared__ unsigned wsumA[32], wsumB[32];
    __shared__ int vcount;
    __shared__ unsigned char slab[NBOX];
    __shared__ unsigned short cws[3][32];

    int f = blockIdx.x, tid = threadIdx.x, lane = tid & 31, wid = tid >> 5;
    const float* sc = scores + f*NBOX;
    if (tid == 0) vcount = 0;
    int vloc = 0;
    for (int i = tid; i < NBOX; i += 1024) {
        float s = sc[i];
        bool v = (s > SCORE_T);
        float skey = v ? s : -INFINITY;
        unsigned u = __float_as_uint(skey);
        u = (u & 0x80000000u) ? ~u : (u | 0x80000000u);
        kb[SKW(i)] = ~u;
        pb[SKW(i)] = (unsigned)i;
        vloc += v ? 1 : 0;
    }
    #pragma unroll
    for (int o = 16; o; o >>= 1) vloc += __shfl_xor_sync(0xffffffffu, vloc, o);
    if (lane == 0 && vloc) atomicAdd(&vcount, vloc);
    __syncthreads();

    int cur = 0;
    for (int pass = 0; pass < 16; ++pass) {
        int sh = pass * 2;
        unsigned* kc = kb + cur*4224;  unsigned* pc = pb + cur*4224;
        unsigned* kn = kb + (cur^1)*4224; unsigned* pn = pb + (cur^1)*4224;
        int b0 = tid*4;
        unsigned k0=kc[SKW(b0)],k1=kc[SKW(b0+1)],k2=kc[SKW(b0+2)],k3=kc[SKW(b0+3)];
        unsigned q0=pc[SKW(b0)],q1=pc[SKW(b0+1)],q2=pc[SKW(b0+2)],q3=pc[SKW(b0+3)];
        int d0=(k0>>sh)&3, d1=(k1>>sh)&3, d2=(k2>>sh)&3, d3=(k3>>sh)&3;
        unsigned cA=0, cB=0;
        #define ADDC(d) { if((d)==0) cA+=1u; else if((d)==1) cA+=(1u<<16); \
                          else if((d)==2) cB+=1u; else cB+=(1u<<16); }
        ADDC(d0) ADDC(d1) ADDC(d2) ADDC(d3)
        unsigned a=cA, b=cB;
        #pragma unroll
        for (int o=1;o<32;o<<=1){
            unsigned ta=__shfl_up_sync(0xffffffffu,a,o);
            unsigned tb=__shfl_up_sync(0xffffffffu,b,o);
            if(lane>=o){a+=ta;b+=tb;}
        }
        if (lane==31){ wsumA[wid]=a; wsumB[wid]=b; }
        __syncthreads();
        if (wid==0){
            unsigned x=wsumA[lane], y=wsumB[lane];
            #pragma unroll
            for(int o=1;o<32;o<<=1){
                unsigned tx=__shfl_up_sync(0xffffffffu,x,o);
                unsigned ty=__shfl_up_sync(0xffffffffu,y,o);
                if(lane>=o){x+=tx;y+=ty;}
            }
            wsumA[lane]=x; wsumB[lane]=y;
        }
        __syncthreads();
        unsigned wa = wid ? wsumA[wid-1] : 0u, wb = wid ? wsumB[wid-1] : 0u;
        unsigned exA = a - cA + wa, exB = b - cB + wb;
        unsigned totA = wsumA[31], totB = wsumB[31];
        unsigned T0 = totA & 0xffffu, T1 = totA >> 16, T2 = totB & 0xffffu;
        unsigned base1 = T0, base2 = T0+T1, base3 = base2+T2;
        unsigned off[4];
        off[0]=(exA&0xffffu); off[1]=base1+(exA>>16);
        off[2]=base2+(exB&0xffffu); off[3]=base3+(exB>>16);
        unsigned dd;
        dd=off[d0]++; kn[SKW(dd)]=k0; pn[SKW(dd)]=q0;
        dd=off[d1]++; kn[SKW(dd)]=k1; pn[SKW(dd)]=q1;
        dd=off[d2]++; kn[SKW(dd)]=k2; pn[SKW(dd)]=q2;
        dd=off[d3]++; kn[SKW(dd)]=k3; pn[SKW(dd)]=q3;
        __syncthreads();
        cur ^= 1;
    }
    int V = vcount;
    if (tid == 0) d_V[f] = V;
    int base = f*NBOX;

    // phase 1: gather into sorted order, write geometry, record labels
    unsigned* pf = pb + cur*4224;
    int r0 = tid*4;
    #pragma unroll
    for (int u = 0; u < 4; ++u) {
        int r = r0 + u;
        int o = (int)pf[SKW(r)];
        const float* bx = boxes + ((size_t)f*NBOX + o)*7;
        float b0 = bx[0], b1 = bx[1], b2 = bx[2], b3 = bx[3],
              b4 = bx[4], b5 = bx[5], b6 = bx[6];
        float s  = sc[o];
        int  lab = labels[f*NBOX + o];
        float off = (float)lab * 10000.0f;
        float cx = b0 + off, cy = b1;
        float hx = b3 * 0.5f, hy = b4 * 0.5f;
        float x1 = cx - hx, x2 = cx + hx, y1 = cy - hy, y2 = cy + hy;
        float area = (x2 - x1) * (y2 - y1);
        int idx = base + r;
        float* sb = d_sbox + (size_t)idx*7;
        sb[0]=b0; sb[1]=b1; sb[2]=b2; sb[3]=b3; sb[4]=b4; sb[5]=b5; sb[6]=b6;
        d_sscore[idx] = s; d_slabel[idx] = (float)lab;
        d_x1[idx]=x1; d_x2[idx]=x2; d_y1[idx]=y1; d_y2[idx]=y2; d_areaA[idx]=area;
        slab[r] = (unsigned char)lab;
    }
    __syncthreads();

    // phase 2: stable per-class compaction of valid boxes (r < V)
    unsigned pk = 0;
    int lb[4];
    #pragma unroll
    for (int u = 0; u < 4; ++u) {
        int r = r0 + u;
        lb[u] = slab[r];
        if (r < V) pk += 1u << (lb[u]*10);
    }
    unsigned inc = pk;
    #pragma unroll
    for (int o=1;o<32;o<<=1){ unsigned t=__shfl_up_sync(0xffffffffu,inc,o); if(lane>=o) inc+=t; }
    unsigned ex = inc - pk;
    if (lane == 31) {
        cws[0][wid] = (unsigned short)( inc        & 1023u);
        cws[1][wid] = (unsigned short)((inc >> 10) & 1023u);
        cws[2][wid] = (unsigned short)((inc >> 20) & 1023u);
    }
    __syncthreads();
    if (tid < 32) {
        #pragma unroll
        for (int c2 = 0; c2 < 3; ++c2) {
            unsigned v = cws[c2][lane];
            #pragma unroll
            for (int o=1;o<32;o<<=1){ unsigned t=__shfl_up_sync(0xffffffffu,v,o); if(lane>=o) v+=t; }
            cws[c2][lane] = (unsigned short)v;
        }
    }
    __syncthreads();
    int offc[3];
    #pragma unroll
    for (int c2 = 0; c2 < 3; ++c2)
        offc[c2] = (wid ? (int)cws[c2][wid-1] : 0) + (int)((ex >> (10*c2)) & 1023u);
    #pragma unroll
    for (int u = 0; u < 4; ++u) {
        int r = r0 + u;
        if (r < V) {
            int c2 = lb[u];
            int p  = offc[c2]++;
            int idx = base + r;
            int ci  = (f*3 + c2)*NBOX + p;
            d_clsGeo [ci] = make_float4(d_x1[idx], d_x2[idx], d_y1[idx], d_y2[idx]);
            d_clsArea[ci] = d_areaA[idx];
            d_clsG   [ci] = r;
        }
    }
    if (tid < 3) d_Vc[f*3 + tid] = (int)cws[tid][31];
}

// ---------------- kernel 2: per-class ascending neighbor lists --------------
__global__ void __launch_bounds__(128) k_nbr()
{
    int f = blockIdx.z, c = blockIdx.y, chunk = blockIdx.x;
    int Vc = d_Vc[f*3 + c];
    int i0 = chunk * 128;
    if (i0 >= Vc) return;
    int tid = threadIdx.x;
    int il  = i0 + tid;
    bool act = il < Vc;
    int cbase = (f*3 + c)*NBOX;
    int base  = f*NBOX;

    float4 gi = make_float4(0,0,0,0);
    float  ai = 0.f;
    int    gidx = 0;
    if (act) { gi = d_clsGeo[cbase+il]; ai = d_clsArea[cbase+il]; gidx = d_clsG[cbase+il]; }

    __shared__ float4 sg[128];
    __shared__ float  sa[128];
    __shared__ int    sgi[128];

    int cnt = 0, sp = 0;
    int* lst = d_nbr + (size_t)(base + gidx) * CAP;

    for (int j0 = 0; j0 < Vc; j0 += 128) {
        __syncthreads();
        int j = j0 + tid;
        if (j < Vc) { sg[tid] = d_clsGeo[cbase+j]; sa[tid] = d_clsArea[cbase+j]; sgi[tid] = d_clsG[cbase+j]; }
        __syncthreads();
        int lim = min(128, Vc - j0);
        if (act) {
            #pragma unroll 4
            for (int jj = 0; jj < lim; ++jj) {
                float4 t = sg[jj];
                float ix = fminf(gi.y, t.y) - fmaxf(gi.x, t.x);
                float iy = fminf(gi.w, t.w) - fmaxf(gi.z, t.z);
                if (ix > 0.f && iy > 0.f) {            // rare path
                    float inter = ix * iy;
                    float den   = fmaxf(ai + sa[jj] - inter, 1e-6f);
                    float iou   = inter / den;          // exact fp32 div (matches ref)
                    if (iou > IOU_T && cnt < CAP) {
                        int jg = sgi[jj];
                        if (jg == gidx) sp = cnt;
                        lst[cnt++] = jg;
                    }
                }
            }
        }
    }
    if (act) { d_deg[base + gidx] = cnt; d_selfpos[base + gidx] = sp; }
}

// ---------------- kernel 3: parallel lex-first greedy, shared-cached --------
__global__ void __launch_bounds__(1024) k_scan()
{
    extern __shared__ char smc[];
    unsigned short* inl  = (unsigned short*)smc;                       // NBOX*INL
    unsigned short* spA  = (unsigned short*)(smc + NBOX*INL*2);        // NBOX
    unsigned short* cid  = spA + NBOX;                                 // NBOX
    unsigned char*  state= (unsigned char*)(cid + NBOX);               // NBOX
    __shared__ int changed;
    volatile unsigned char* vstate = state;

    int f = blockIdx.x, tid = threadIdx.x;
    int base = f*NBOX;
    int V = d_V[f];

    for (int i = tid; i < NBOX; i += 1024) {
        d_lead[base + i] = 0;
        state[i] = (i < V) ? (unsigned char)0 : (unsigned char)2;
    }
    for (int i = tid; i < V; i += 1024) {
        int sp = d_selfpos[base + i];
        spA[i] = (unsigned short)sp;
        const int* g = d_nbr + (size_t)(base + i) * CAP;
        int m = sp < INL ? sp : INL;
        for (int k = 0; k < m; ++k) inl[i*INL + k] = (unsigned short)g[k];
    }
    __syncthreads();

    for (int round = 0; round < 4096; ++round) {
        if (tid == 0) changed = 0;
        __syncthreads();
        for (int rep = 0; rep < 2; ++rep) {
            int i0 = tid * 4;
            #pragma unroll
            for (int u = 0; u < 4; ++u) {
                int i = i0 + u;
                if (vstate[i] != 0) continue;
                int sp = spA[i];
                bool any1 = false, any0 = false;
                int m = sp < INL ? sp : INL;
                for (int k = 0; k < m; ++k) {
                    unsigned char s = vstate[inl[i*INL + k]];
                    any1 |= (s == 1); any0 |= (s == 0);
                }
                if (sp > INL && !any1) {
                    const int* g = d_nbr + (size_t)(base + i) * CAP;
                    for (int k = INL; k < sp && !any1; ++k) {
                        unsigned char s = vstate[g[k]];
                        any1 |= (s == 1); any0 |= (s == 0);
                    }
                }
                if (any1)       { vstate[i] = 2; changed = 1; }
                else if (!any0) { vstate[i] = 1; changed = 1; }
            }
        }
        __syncthreads();
        if (!changed) break;
        __syncthreads();
    }

    for (int i = tid; i < V; i += 1024) {
        if (state[i] == 1) { cid[i] = (unsigned short)i; continue; }
        int sp = spA[i];
        int c = 0xFFFF;
        int m = sp < INL ? sp : INL;
        for (int k = 0; k < m; ++k) {
            int j = inl[i*INL + k];
            if (state[j] == 1) { c = j; break; }
        }
        if (c == 0xFFFF && sp > INL) {
            const int* g = d_nbr + (size_t)(base + i) * CAP;
            for (int k = INL; k < sp; ++k) {
                int j = g[k];
                if (state[j] == 1) { c = j; break; }
            }
        }
        cid[i] = (unsigned short)c;
    }
    __syncthreads();

    for (int i = tid; i < V; i += 1024) {
        if (state[i] != 1) continue;
        int* outl = d_clusIdx + (base + i)*MAXC;
        outl[0] = i;
        const int* lst = d_nbr + (size_t)(base + i) * CAP;
        int sp = spA[i], dg = d_deg[base + i];
        int r = 1;
        for (int k = sp + 1; k < dg; ++k) {
            int m = lst[k];
            if (cid[m] == (unsigned short)i) { if (r < MAXC) outl[r] = m; ++r; }
        }
        d_count[base + i] = (r < MAXC) ? r : MAXC;
        d_lead [base + i] = 1;
    }
}

// ---------------- kernel 4: MLP + softmax merge + output --------------------
__global__ void __launch_bounds__(256) k_merge(const float* __restrict__ W1,
                                               const float* __restrict__ b1,
                                               const float* __restrict__ W2,
                                               const float* __restrict__ b2,
                                               float* __restrict__ out, int writeLead)
{
    __shared__ float sW1[448], sb1[64], sW2[64];
    __shared__ float sb2;
    int tid = threadIdx.x;
    int g = tid >> 4, l = tid & 15;
    unsigned gm = 0xFFFFu << (tid & 16);
    int row = blockIdx.x * 16 + g;
    int lead = d_lead[row];
    int cnt  = lead ? d_count[row] : 0;

    int need = __syncthreads_or(cnt >= 2);
    if (need) {
        for (int t = tid; t < 448; t += 256) sW1[t] = W1[t];
        if (tid < 64) { sb1[tid] = b1[tid]; sW2[tid] = W2[tid]; }
        if (tid == 0) sb2 = b2[0];
        __syncthreads();
    }

    float* infoOut = out + (size_t)row * 9;
    if (!lead) {
        if (l == 0) {
            #pragma unroll
            for (int d = 0; d < 9; ++d) infoOut[d] = 0.f;
            if (writeLead) out[(size_t)NFRAME*NBOX*9 + row] = 0.f;
        }
        return;
    }
    if (cnt == 1) {
        if (l == 0) {
            const float* own = d_sbox + (size_t)row * 7;
            infoOut[0]=own[0]; infoOut[1]=own[1]; infoOut[2]=own[2];
            infoOut[3]=own[3]; infoOut[4]=own[4]; infoOut[5]=own[5];
            infoOut[6]=own[6];
            infoOut[7]=d_sscore[row];
            infoOut[8]=d_slabel[row];
            if (writeLead) out[(size_t)NFRAME*NBOX*9 + row] = 1.f;
        }
        return;
    }
    bool ok = l < cnt;
    float c[7];
    int f = row >> 12;
    if (ok) {
        int nb = d_clusIdx[row*MAXC + l];
        const float* sp = d_sbox + ((size_t)(f*NBOX) + nb) * 7;
        #pragma unroll
        for (int d = 0; d < 7; ++d) c[d] = sp[d];
    } else {
        #pragma unroll
        for (int d = 0; d < 7; ++d) c[d] = 0.f;
    }
    float logit;
    if (ok) {
        float lg = 0.f;
        for (int k = 0; k < 64; ++k) {
            float h = sb1[k];
            #pragma unroll
            for (int d = 0; d < 7; ++d) h += c[d] * sW1[d*64 + k];
            h = fmaxf(h, 0.f);
            lg += h * sW2[k];
        }
        logit = lg + sb2;
    } else logit = -1e9f;

    float m = logit;
    #pragma unroll
    for (int o = 8; o; o >>= 1) m = fmaxf(m, __shfl_xor_sync(gm, m, o, 16));
    float p = ok ? expf(logit - m) : 0.f;
    float S = p;
    #pragma unroll
    for (int o = 8; o; o >>= 1) S += __shfl_xor_sync(gm, S, o, 16);
    float w = p / S;
    float mg[7];
    #pragma unroll
    for (int d = 0; d < 7; ++d) {
        float v = w * c[d];
        #pragma unroll
        for (int o = 8; o; o >>= 1) v += __shfl_xor_sync(gm, v, o, 16);
        mg[d] = v;
    }
    if (l == 0) {
        const float* own = d_sbox + (size_t)row * 7;
        infoOut[0] = mg[0]; infoOut[1] = mg[1]; infoOut[2] = mg[2];
        infoOut[3] = (mg[3] <= 0.f) ? own[3] : mg[3];
        infoOut[4] = (mg[4] <= 0.f) ? own[4] : mg[4];
        infoOut[5] = (mg[5] <= 0.f) ? own[5] : mg[5];
        infoOut[6] = mg[6];
        infoOut[7] = d_sscore[row];
        infoOut[8] = d_slabel[row];
        if (writeLead) out[(size_t)NFRAME*NBOX*9 + row] = 1.f;
    }
}

// ---------------- launch -----------------------------------------------------
extern "C" void kernel_launch(void* const* d_in, const int* in_sizes, int n_in,
                              void* d_out, int out_size)
{
    const float* boxes  = (const float*)d_in[0];
    const float* scores = (const float*)d_in[1];
    const int*   labels = (const int*)  d_in[2];
    const float* W1     = (const float*)d_in[3];
    const float* b1     = (const float*)d_in[4];
    const float* W2     = (const float*)d_in[5];
    const float* b2     = (const float*)d_in[6];
    float* out = (float*)d_out;

    int writeLead = (out_size >= NFRAME*NBOX*10) ? 1 : 0;

    const int SMEM_SORT = 4*4224*4;                               // 67584
    const int SMEM_SCAN = NBOX*INL*2 + NBOX*2*2 + NBOX;           // 86016
    static int inited = 0;
    if (!inited) {
        cudaFuncSetAttribute(k_sort, cudaFuncAttributeMaxDynamicSharedMemorySize, SMEM_SORT);
        cudaFuncSetAttribute(k_scan, cudaFuncAttributeMaxDynamicSharedMemorySize, SMEM_SCAN);
        inited = 1;
    }

    k_sort<<<NFRAME, 1024, SMEM_SORT>>>(boxes, scores, labels);
    k_nbr<<<dim3(32, 3, NFRAME), 128>>>();
    k_scan<<<NFRAME, 1024, SMEM_SCAN>>>();
    k_merge<<<(NFRAME*NBOX)/16, 256>>>(W1, b1, W2, b2, out, writeLead);
}